// round 3
// baseline (speedup 1.0000x reference)
#include <cuda_runtime.h>
#include <cuda_bf16.h>

// Problem constants
#define BATCH   8
#define IN_P    16     // in_planes
#define REP_C   16     // PROD_DW / IN_PLANES
#define OUT_P   32     // out_planes
#define HW      1024   // 32*32
#define PV      256    // HW / 4 (float4 pixel-vecs)
#define C_X     256    // PROD_DW channels of x
#define C_OUT1  8192   // OUT_P * PROD_DW

#define OUT1_VECS ((size_t)BATCH * C_OUT1 * PV)   // 16777216 float4

__global__ __launch_bounds__(256, 6) void qconv_pw_kernel(
    const float4* __restrict__ x,      // (B, 256, 1024) as (B,256,256) float4
    const float4* __restrict__ x2,     // (B, 16, 1024)  as (B,16,256) float4
    const float*  __restrict__ w,      // (32,16)
    float4* __restrict__ out)          // out1 vecs then out2 vecs
{
    const int blk = blockIdx.x;        // 0..1023
    const int iq  = blk & 3;           // i-quarter
    const int o   = (blk >> 2) & 31;
    const int b   = blk >> 7;
    const int p   = threadIdx.x;       // pixel-vec 0..255

    __shared__ float ws[IN_P];
    if (threadIdx.x < IN_P) ws[threadIdx.x] = w[o * IN_P + threadIdx.x];
    __syncthreads();

    const float4* xb   = x   + (size_t)b * C_X * PV + p;
    float4*       out1 = out + ((size_t)b * C_OUT1 + (size_t)o * 256) * PV + p;

    #pragma unroll
    for (int ii = 0; ii < 4; ii++) {
        const int i = iq * 4 + ii;
        const float wv = ws[i];
        const float4* xc = xb + (size_t)(i * REP_C) * PV;
        float4* dst = out1 + (size_t)(i * REP_C) * PV;

        // Pass 1: threshold sum of products (reference rounding order: sum of
        // w*x_r). Loads go to L1; only 4 accumulators stay live.
        float tx = 0.f, ty = 0.f, tz = 0.f, tw = 0.f;
        #pragma unroll
        for (int r = 0; r < REP_C; r++) {
            const float4 v = __ldg(&xc[(size_t)r * PV]);
            tx += wv * v.x;
            ty += wv * v.y;
            tz += wv * v.z;
            tw += wv * v.w;
        }

        const float gx = (tx > 0.f) ? wv : 0.f;
        const float gy = (ty > 0.f) ? wv : 0.f;
        const float gz = (tz > 0.f) ? wv : 0.f;
        const float gw = (tw > 0.f) ? wv : 0.f;

        // Pass 2: reload from L1 (persists within launch), scale, stream out.
        #pragma unroll
        for (int r = 0; r < REP_C; r++) {
            const float4 v = __ldg(&xc[(size_t)r * PV]);
            float4 s;
            s.x = gx * v.x;
            s.y = gy * v.y;
            s.z = gz * v.z;
            s.w = gw * v.w;
            __stcs(&dst[(size_t)r * PV], s);
        }
    }

    // Dense 1x1 conv + ReLU path (tiny): iq==0 blocks handle it.
    if (iq == 0) {
        const float4* x2b = x2 + (size_t)b * IN_P * PV + p;
        float ax = 0.f, ay = 0.f, az = 0.f, aw = 0.f;
        #pragma unroll
        for (int i = 0; i < IN_P; i++) {
            const float4 v = __ldg(&x2b[(size_t)i * PV]);
            const float wv = ws[i];
            ax = fmaf(wv, v.x, ax);
            ay = fmaf(wv, v.y, ay);
            az = fmaf(wv, v.z, az);
            aw = fmaf(wv, v.w, aw);
        }
        float4 r;
        r.x = fmaxf(ax, 0.f);
        r.y = fmaxf(ay, 0.f);
        r.z = fmaxf(az, 0.f);
        r.w = fmaxf(aw, 0.f);
        out[OUT1_VECS + ((size_t)b * OUT_P + o) * PV + p] = r;
    }
}

extern "C" void kernel_launch(void* const* d_in, const int* in_sizes, int n_in,
                              void* d_out, int out_size)
{
    const float4* x  = (const float4*)d_in[0];
    const float4* x2 = (const float4*)d_in[1];
    const float*  w  = (const float*) d_in[2];
    float4* out = (float4*)d_out;

    qconv_pw_kernel<<<BATCH * OUT_P * 4, 256>>>(x, x2, w, out);
}

// round 4
// speedup vs baseline: 2.7329x; 2.7329x over previous
#include <cuda_runtime.h>
#include <cuda_bf16.h>

// Problem constants
#define BATCH   8
#define IN_P    16     // in_planes
#define REP_C   16     // PROD_DW / IN_PLANES
#define OUT_P   32     // out_planes
#define PV      256    // 32*32 pixels / 4 (float4 pixel-vecs)
#define C_X     256    // PROD_DW channels of x
#define C_OUT1  8192   // OUT_P * PROD_DW
#define O_PER_BLK 4    // o values per block

#define OUT1_VECS ((size_t)BATCH * C_OUT1 * PV)   // 16777216 float4

// Block = (b, i, o-chunk). Thread = one pixel-vec. x slice for (b,i) is loaded
// into registers ONCE and reused for all O_PER_BLK output channels, cutting the
// 32x L2 read amplification of the naive mapping down to 8x.
__global__ __launch_bounds__(256) void qconv_pw_kernel(
    const float4* __restrict__ x,      // (B,256,1024) -> (B,256,256) float4
    const float4* __restrict__ x2,     // (B,16,1024)  -> (B,16,256)  float4
    const float*  __restrict__ w,      // (32,16)
    float4* __restrict__ out)          // out1 vecs then out2 vecs
{
    const int blk = blockIdx.x;        // 0..1023
    const int oc  = blk & 7;           // o-chunk (4 o each)
    const int i   = (blk >> 3) & 15;   // in-plane
    const int b   = blk >> 7;          // batch
    const int p   = threadIdx.x;       // pixel-vec 0..255

    __shared__ float ws[OUT_P * IN_P];
    ws[p] = w[p];
    ws[p + 256] = w[p + 256];
    __syncthreads();

    // Load the 16 rep-channels for this (b,i) pixel-vec; keep in registers
    // across the whole o loop.
    const float4* xc = x + ((size_t)b * C_X + (size_t)i * REP_C) * PV + p;
    float4 xr[REP_C];
    #pragma unroll
    for (int r = 0; r < REP_C; r++)
        xr[r] = __ldg(&xc[(size_t)r * PV]);

    float4* ob = out + ((size_t)b * C_OUT1 + (size_t)i * REP_C) * PV + p;

    #pragma unroll
    for (int oo = 0; oo < O_PER_BLK; oo++) {
        const int o = oc * O_PER_BLK + oo;
        const float wv = ws[o * IN_P + i];

        // Threshold sum in the reference's exact order: sequential sum of the
        // PRODUCTS w*x_r over r = 0..15.
        float tx = 0.f, ty = 0.f, tz = 0.f, tw = 0.f;
        #pragma unroll
        for (int r = 0; r < REP_C; r++) {
            tx += wv * xr[r].x;
            ty += wv * xr[r].y;
            tz += wv * xr[r].z;
            tw += wv * xr[r].w;
        }

        const float gx = (tx > 0.f) ? wv : 0.f;
        const float gy = (ty > 0.f) ? wv : 0.f;
        const float gz = (tz > 0.f) ? wv : 0.f;
        const float gw = (tw > 0.f) ? wv : 0.f;

        float4* dst = ob + (size_t)o * (C_X * PV);
        #pragma unroll
        for (int r = 0; r < REP_C; r++) {
            float4 s;
            s.x = gx * xr[r].x;
            s.y = gy * xr[r].y;
            s.z = gz * xr[r].z;
            s.w = gw * xr[r].w;
            __stcs(&dst[(size_t)r * PV], s);   // streaming: never re-read
        }
    }

    // Dense 1x1 conv + ReLU path (tiny). i==0 blocks compute it for their 4 o.
    if (i == 0) {
        const float4* x2b = x2 + (size_t)b * IN_P * PV + p;
        float ax[O_PER_BLK], ay[O_PER_BLK], az[O_PER_BLK], aw[O_PER_BLK];
        #pragma unroll
        for (int oo = 0; oo < O_PER_BLK; oo++)
            ax[oo] = ay[oo] = az[oo] = aw[oo] = 0.f;

        #pragma unroll
        for (int ii = 0; ii < IN_P; ii++) {   // sequential i: matches einsum
            const float4 v = __ldg(&x2b[(size_t)ii * PV]);
            #pragma unroll
            for (int oo = 0; oo < O_PER_BLK; oo++) {
                const float wv = ws[(oc * O_PER_BLK + oo) * IN_P + ii];
                ax[oo] = fmaf(wv, v.x, ax[oo]);
                ay[oo] = fmaf(wv, v.y, ay[oo]);
                az[oo] = fmaf(wv, v.z, az[oo]);
                aw[oo] = fmaf(wv, v.w, aw[oo]);
            }
        }
        #pragma unroll
        for (int oo = 0; oo < O_PER_BLK; oo++) {
            float4 r;
            r.x = fmaxf(ax[oo], 0.f);
            r.y = fmaxf(ay[oo], 0.f);
            r.z = fmaxf(az[oo], 0.f);
            r.w = fmaxf(aw[oo], 0.f);
            out[OUT1_VECS + ((size_t)b * OUT_P + oc * O_PER_BLK + oo) * PV + p] = r;
        }
    }
}

extern "C" void kernel_launch(void* const* d_in, const int* in_sizes, int n_in,
                              void* d_out, int out_size)
{
    const float4* x  = (const float4*)d_in[0];
    const float4* x2 = (const float4*)d_in[1];
    const float*  w  = (const float*) d_in[2];
    float4* out = (float4*)d_out;

    qconv_pw_kernel<<<BATCH * IN_P * 8, 256>>>(x, x2, w, out);
}